// round 15
// baseline (speedup 1.0000x reference)
#include <cuda_runtime.h>
#include <cuda_bf16.h>

// Problem constants
#define Bn 4
#define Hn 480
#define Wn 640
#define HWn (Hn * Wn)          // 307200
#define PWn (Wn + 2)           // 642
#define PHn (Hn + 2)           // 482
#define PHWn (PHn * PWn)       // 309444
#define PROP_TIME 18
#define TAIL 704

// Tiling: 64x8 tiles -> 1200 blocks per pair-launch (full occupancy).
#define TILE_W 64
#define TILE_H 8
#define HALO 9
#define RX (TILE_W + 2 * HALO)   // 82
#define RY (TILE_H + 2 * HALO)   // 26
#define SSTR 83                  // smem row stride in float2; gcd(83,32)=1

// OOB sentinel tap: yoff=481 (zero border row), xoff=0.
#define SENT_Y (PHn - 1)

// Static scratch: ping-pong padded feature buffers g = f*conf_eff.
__device__ float g_bufA[Bn * PHWn + TAIL];
__device__ float g_bufB[Bn * PHWn + TAIL];
// Packed taps, layout [b][tap][pix], 8 B each:
//   w0: yoff(9) | xoff(10)<<9 | wxq(13)<<19
//   w1: wyq(13) | affq(signed 19)<<13
__device__ unsigned long long g_taps[(size_t)Bn * 8 * HWn];
// Fused fix/conf: q<0 -> fixed value -q; q>=0 -> conf=q.
__device__ float g_q[Bn * HWn];

// ---------------------------------------------------------------------------
// Precompute (idempotent; replayed each graph launch).
// ---------------------------------------------------------------------------
__global__ __launch_bounds__(256)
void prep_kernel(const float* __restrict__ feat_init,
                 const float* __restrict__ guid,
                 const float* __restrict__ conf,
                 const float* __restrict__ fix,
                 const float* __restrict__ scale_ptr)
{
    int idx = blockIdx.x * blockDim.x + threadIdx.x;
    if (idx >= Bn * PHWn + TAIL) return;

    int b = idx / PHWn;
    int r = idx - b * PHWn;
    int yy = r / PWn;
    int xx = r - yy * PWn;

    bool is_tail = (idx >= Bn * PHWn);
    if (is_tail || yy == 0 || yy == PHn - 1 || xx == 0 || xx == PWn - 1) {
        g_bufA[idx] = 0.0f;
        g_bufB[idx] = 0.0f;
        return;
    }

    int y = yy - 1, x = xx - 1;
    int pix = y * Wn + x;

    // Affinity normalization (guidance channels 16..23)
    float scale = scale_ptr[0] + 1e-8f;
    float inv_scale = 1.0f / scale;
    const float* gbase = guid + ((size_t)b * 24) * HWn + pix;
    float a[8];
    float s = 1e-4f;
#pragma unroll
    for (int k = 0; k < 8; k++) {
        float v = tanhf(gbase[(16 + k) * HWn]) * inv_scale;
        a[k] = v;
        s += fabsf(v);
    }
    s = fmaxf(s, 1.0f);
    float invs = 1.0f / s;

#pragma unroll
    for (int t = 0; t < 8; t++) {
        const int kt = (t < 4) ? t : t + 1;
        const float ky = (float)(kt / 3 - 1);
        const float kx = (float)(kt % 3 - 1);

        float dy = gbase[(2 * t) * HWn];
        float dx = gbase[(2 * t + 1) * HWn];

        float py = (float)y + ky + dy;
        float px = (float)x + kx + dx;
        float y0f = floorf(py);
        float x0f = floorf(px);
        int iy = (int)y0f;
        int ix = (int)x0f;
        float wy = py - y0f;
        float wx = px - x0f;

        bool valid = (iy >= -1) & (iy <= Hn - 1) & (ix >= -1) & (ix <= Wn - 1);
        int yoff = valid ? (iy + 1) : SENT_Y;
        int xoff = valid ? (ix + 1) : 0;

        int wxq = min((int)(wx * 8192.0f + 0.5f), 8191);
        int wyq = min((int)(wy * 8192.0f + 0.5f), 8191);
        int affq = (int)rintf(a[t] * invs * 131072.0f);

        unsigned int w0 = (unsigned int)yoff | ((unsigned int)xoff << 9)
                        | ((unsigned int)wxq << 19);
        unsigned int w1 = (unsigned int)wyq | ((unsigned int)affq << 13);
        g_taps[(size_t)(b * 8 + t) * HWn + pix] =
            ((unsigned long long)w1 << 32) | w0;
    }

    int gidx = b * HWn + pix;
    float fv = fix[gidx];
    bool m = fv > 0.0f;
    float cf = conf[gidx];
    float f0 = m ? fv : feat_init[gidx];
    float ce = m ? 1.0f : cf;
    g_bufA[idx] = f0 * ce;
    g_q[gidx] = m ? -fv : cf;
}

// ---------------------------------------------------------------------------
// One propagation step for TWO batches (pairBase, pairBase+1).
// SMEM staging holds float2 pairs (g[j], g[j+1]) so each bilinear corner row
// is ONE 64-bit LDS.
// ---------------------------------------------------------------------------
__global__ __launch_bounds__(256)
void iter_kernel(float* __restrict__ outF, int srcIsA, int write_out, int pairBase)
{
    __shared__ float2 sm2[RY * SSTR];   // 17.3 KB

    int tid = threadIdx.x;
    int b   = pairBase + blockIdx.z;
    int tx0 = blockIdx.x * TILE_W;
    int ty0 = blockIdx.y * TILE_H;

    const float* __restrict__ gIn  = (srcIsA ? g_bufA : g_bufB) + (size_t)b * PHWn;
    float* __restrict__       gOut = (srcIsA ? g_bufB : g_bufA) + (size_t)b * PHWn;

    const int by0 = ty0 + 1 - HALO;
    const int bx0 = tx0 + 1 - HALO;

    // Stage region as (g[j], g[j+1]) pairs; zero outside padded buffer.
    for (int i = tid; i < RY * RX; i += 256) {
        int row = i / RX;
        int col = i - row * RX;
        int gy = by0 + row;
        int gx = bx0 + col;
        float v0 = 0.0f, v1 = 0.0f;
        if ((unsigned)gy < (unsigned)PHn && (unsigned)gx < (unsigned)PWn) {
            const float* p = gIn + gy * PWn + gx;
            v0 = p[0];
            v1 = p[1];     // safe: TAIL padding past last batch
        }
        sm2[row * SSTR + col] = make_float2(v0, v1);
    }
    __syncthreads();

#pragma unroll
    for (int k = 0; k < (TILE_W * TILE_H) / 256; k++) {
        int pixt = tid + k * 256;
        int row = pixt >> 6;            // TILE_W = 64
        int col = pixt & 63;
        int y = ty0 + row;
        int x = tx0 + col;
        int r = y * Wn + x;
        int gidx = b * HWn + r;

        const unsigned long long* tp = g_taps + (size_t)(b * 8) * HWn + r;

        float acc = 0.0f;
        float asum = 0.0f;

#pragma unroll
        for (int t = 0; t < 8; t++) {
            unsigned long long w = __ldg(tp + (size_t)t * HWn);
            unsigned int w0 = (unsigned int)w;
            unsigned int w1 = (unsigned int)(w >> 32);
            int yoff = (int)(w0 & 511u);
            int xoff = (int)((w0 >> 9) & 1023u);
            float wx = (float)(w0 >> 19) * (1.0f / 8192.0f);
            float wy = (float)(w1 & 8191u) * (1.0f / 8192.0f);
            float av = (float)(((int)w1) >> 13) * (1.0f / 131072.0f);

            int ly = yoff - by0;
            int lx = xoff - bx0;
            float v00, v01, v10, v11;
            if ((unsigned)ly < (unsigned)(RY - 1) &&
                (unsigned)lx < (unsigned)(RX - 1)) {
                int s = ly * SSTR + lx;
                float2 top2 = sm2[s];
                float2 bot2 = sm2[s + SSTR];
                v00 = top2.x; v01 = top2.y;
                v10 = bot2.x; v11 = bot2.y;
            } else {
                const float* p = gIn + yoff * PWn + xoff;
                v00 = p[0];
                v01 = p[1];
                v10 = p[PWn];
                v11 = p[PWn + 1];
            }
            float top = fmaf(wx, v01 - v00, v00);
            float bot = fmaf(wx, v11 - v10, v10);
            float v = fmaf(wy, bot - top, top);
            acc = fmaf(av, v, acc);
            asum += av;
        }

        // Center tap: exact sample; affinity = 1 - sum(aff8).
        float c = sm2[(row + HALO) * SSTR + (col + HALO)].x;
        acc = fmaf(1.0f - asum, c, acc);

        float qv = __ldg(g_q + gidx);
        bool m = qv < 0.0f;
        float fn = m ? -qv : acc;

        if (write_out) {
            outF[gidx] = fn;
        } else {
            float gv = m ? fn : fn * qv;
            gOut[(y + 1) * PWn + (x + 1)] = gv;
        }
    }
}

extern "C" void kernel_launch(void* const* d_in, const int* in_sizes, int n_in,
                              void* d_out, int out_size)
{
    const float* feat_init  = (const float*)d_in[0];
    const float* guidance   = (const float*)d_in[1];
    const float* confidence = (const float*)d_in[2];
    const float* feat_fix   = (const float*)d_in[3];
    const float* aff_scale  = (const float*)d_in[4];
    float* out = (float*)d_out;

    const int threads = 256;
    const int prep_blocks = (Bn * PHWn + TAIL + threads - 1) / threads;
    prep_kernel<<<prep_blocks, threads>>>(feat_init, guidance, confidence,
                                          feat_fix, aff_scale);

    dim3 gridI(Wn / TILE_W, Hn / TILE_H, 2);   // 10 x 60 x 2 = 1200 blocks
    // Batch pair {0,1} full propagation, then pair {2,3}: keeps each pair's
    // tap stream (~47 MB) L2-resident across its 18 steps.
    for (int pair = 0; pair < 2; pair++) {
        int srcIsA = 1;
        for (int t = 0; t < PROP_TIME; t++) {
            int last = (t == PROP_TIME - 1) ? 1 : 0;
            iter_kernel<<<gridI, threads>>>(out, srcIsA, last, pair * 2);
            srcIsA ^= 1;
        }
    }
}

// round 16
// speedup vs baseline: 1.1601x; 1.1601x over previous
#include <cuda_runtime.h>
#include <cuda_bf16.h>

// Problem constants
#define Bn 4
#define Hn 480
#define Wn 640
#define HWn (Hn * Wn)          // 307200
#define PWn (Wn + 2)           // 642
#define PHn (Hn + 2)           // 482
#define PHWn (PHn * PWn)       // 309444
#define PROP_TIME 18
#define TAIL 704

// Tiling: 64x8 tiles, full batch -> 10x60x4 = 2400 blocks/launch.
#define TILE_W 64
#define TILE_H 8
#define HALO 9
#define RX (TILE_W + 2 * HALO)   // 82
#define RY (TILE_H + 2 * HALO)   // 26
#define SSTR 83                  // smem row stride in float2; gcd(83,32)=1

// OOB sentinel tap: yoff=481 (zero border row), xoff=0.
#define SENT_Y (PHn - 1)

// Static scratch: ping-pong padded feature buffers g = f*conf_eff.
__device__ float g_bufA[Bn * PHWn + TAIL];
__device__ float g_bufB[Bn * PHWn + TAIL];
// Packed taps, layout [b][tap][pix], 8 B each:
//   w0: yoff(9) | xoff(10)<<9 | wxq(13)<<19
//   w1: wyq(13) | affq(signed 19)<<13
__device__ unsigned long long g_taps[(size_t)Bn * 8 * HWn];
// Fused fix/conf: q<0 -> fixed value -q; q>=0 -> conf=q.
__device__ float g_q[Bn * HWn];

// ---------------------------------------------------------------------------
// Precompute (idempotent; replayed each graph launch).
// ---------------------------------------------------------------------------
__global__ __launch_bounds__(256)
void prep_kernel(const float* __restrict__ feat_init,
                 const float* __restrict__ guid,
                 const float* __restrict__ conf,
                 const float* __restrict__ fix,
                 const float* __restrict__ scale_ptr)
{
    int idx = blockIdx.x * blockDim.x + threadIdx.x;
    if (idx >= Bn * PHWn + TAIL) return;

    int b = idx / PHWn;
    int r = idx - b * PHWn;
    int yy = r / PWn;
    int xx = r - yy * PWn;

    bool is_tail = (idx >= Bn * PHWn);
    if (is_tail || yy == 0 || yy == PHn - 1 || xx == 0 || xx == PWn - 1) {
        g_bufA[idx] = 0.0f;
        g_bufB[idx] = 0.0f;
        return;
    }

    int y = yy - 1, x = xx - 1;
    int pix = y * Wn + x;

    // Affinity normalization (guidance channels 16..23)
    float scale = scale_ptr[0] + 1e-8f;
    float inv_scale = 1.0f / scale;
    const float* gbase = guid + ((size_t)b * 24) * HWn + pix;
    float a[8];
    float s = 1e-4f;
#pragma unroll
    for (int k = 0; k < 8; k++) {
        float v = tanhf(gbase[(16 + k) * HWn]) * inv_scale;
        a[k] = v;
        s += fabsf(v);
    }
    s = fmaxf(s, 1.0f);
    float invs = 1.0f / s;

#pragma unroll
    for (int t = 0; t < 8; t++) {
        const int kt = (t < 4) ? t : t + 1;
        const float ky = (float)(kt / 3 - 1);
        const float kx = (float)(kt % 3 - 1);

        float dy = gbase[(2 * t) * HWn];
        float dx = gbase[(2 * t + 1) * HWn];

        float py = (float)y + ky + dy;
        float px = (float)x + kx + dx;
        float y0f = floorf(py);
        float x0f = floorf(px);
        int iy = (int)y0f;
        int ix = (int)x0f;
        float wy = py - y0f;
        float wx = px - x0f;

        bool valid = (iy >= -1) & (iy <= Hn - 1) & (ix >= -1) & (ix <= Wn - 1);
        int yoff = valid ? (iy + 1) : SENT_Y;
        int xoff = valid ? (ix + 1) : 0;

        int wxq = min((int)(wx * 8192.0f + 0.5f), 8191);
        int wyq = min((int)(wy * 8192.0f + 0.5f), 8191);
        int affq = (int)rintf(a[t] * invs * 131072.0f);

        unsigned int w0 = (unsigned int)yoff | ((unsigned int)xoff << 9)
                        | ((unsigned int)wxq << 19);
        unsigned int w1 = (unsigned int)wyq | ((unsigned int)affq << 13);
        g_taps[(size_t)(b * 8 + t) * HWn + pix] =
            ((unsigned long long)w1 << 32) | w0;
    }

    int gidx = b * HWn + pix;
    float fv = fix[gidx];
    bool m = fv > 0.0f;
    float cf = conf[gidx];
    float f0 = m ? fv : feat_init[gidx];
    float ce = m ? 1.0f : cf;
    g_bufA[idx] = f0 * ce;
    g_q[gidx] = m ? -fv : cf;
}

// ---------------------------------------------------------------------------
// One propagation step, full batch. SMEM staging holds float2 pairs
// (g[j], g[j+1]) so each bilinear corner row is ONE 64-bit LDS.
// __launch_bounds__(256, 6) pins regs so occupancy reaches 6 blocks/SM.
// ---------------------------------------------------------------------------
__global__ __launch_bounds__(256, 6)
void iter_kernel(float* __restrict__ outF, int srcIsA, int write_out)
{
    __shared__ float2 sm2[RY * SSTR];   // 17.3 KB

    int tid = threadIdx.x;
    int b   = blockIdx.z;
    int tx0 = blockIdx.x * TILE_W;
    int ty0 = blockIdx.y * TILE_H;

    const float* __restrict__ gIn  = (srcIsA ? g_bufA : g_bufB) + (size_t)b * PHWn;
    float* __restrict__       gOut = (srcIsA ? g_bufB : g_bufA) + (size_t)b * PHWn;

    const int by0 = ty0 + 1 - HALO;
    const int bx0 = tx0 + 1 - HALO;

    // Stage region as (g[j], g[j+1]) pairs; zero outside padded buffer.
    for (int i = tid; i < RY * RX; i += 256) {
        int row = i / RX;
        int col = i - row * RX;
        int gy = by0 + row;
        int gx = bx0 + col;
        float v0 = 0.0f, v1 = 0.0f;
        if ((unsigned)gy < (unsigned)PHn && (unsigned)gx < (unsigned)PWn) {
            const float* p = gIn + gy * PWn + gx;
            v0 = p[0];
            v1 = p[1];     // safe: TAIL padding past last batch
        }
        sm2[row * SSTR + col] = make_float2(v0, v1);
    }
    __syncthreads();

#pragma unroll
    for (int k = 0; k < (TILE_W * TILE_H) / 256; k++) {
        int pixt = tid + k * 256;
        int row = pixt >> 6;            // TILE_W = 64
        int col = pixt & 63;
        int y = ty0 + row;
        int x = tx0 + col;
        int r = y * Wn + x;
        int gidx = b * HWn + r;

        const unsigned long long* tp = g_taps + (size_t)(b * 8) * HWn + r;

        float acc = 0.0f;
        float asum = 0.0f;

#pragma unroll
        for (int t = 0; t < 8; t++) {
            unsigned long long w = __ldg(tp + (size_t)t * HWn);
            unsigned int w0 = (unsigned int)w;
            unsigned int w1 = (unsigned int)(w >> 32);
            int yoff = (int)(w0 & 511u);
            int xoff = (int)((w0 >> 9) & 1023u);
            float wx = (float)(w0 >> 19) * (1.0f / 8192.0f);
            float wy = (float)(w1 & 8191u) * (1.0f / 8192.0f);
            float av = (float)(((int)w1) >> 13) * (1.0f / 131072.0f);

            int ly = yoff - by0;
            int lx = xoff - bx0;
            float v00, v01, v10, v11;
            if ((unsigned)ly < (unsigned)(RY - 1) &&
                (unsigned)lx < (unsigned)(RX - 1)) {
                int s = ly * SSTR + lx;
                float2 top2 = sm2[s];
                float2 bot2 = sm2[s + SSTR];
                v00 = top2.x; v01 = top2.y;
                v10 = bot2.x; v11 = bot2.y;
            } else {
                const float* p = gIn + yoff * PWn + xoff;
                v00 = p[0];
                v01 = p[1];
                v10 = p[PWn];
                v11 = p[PWn + 1];
            }
            float top = fmaf(wx, v01 - v00, v00);
            float bot = fmaf(wx, v11 - v10, v10);
            float v = fmaf(wy, bot - top, top);
            acc = fmaf(av, v, acc);
            asum += av;
        }

        // Center tap: exact sample; affinity = 1 - sum(aff8).
        float c = sm2[(row + HALO) * SSTR + (col + HALO)].x;
        acc = fmaf(1.0f - asum, c, acc);

        float qv = __ldg(g_q + gidx);
        bool m = qv < 0.0f;
        float fn = m ? -qv : acc;

        if (write_out) {
            outF[gidx] = fn;
        } else {
            float gv = m ? fn : fn * qv;
            gOut[(y + 1) * PWn + (x + 1)] = gv;
        }
    }
}

extern "C" void kernel_launch(void* const* d_in, const int* in_sizes, int n_in,
                              void* d_out, int out_size)
{
    const float* feat_init  = (const float*)d_in[0];
    const float* guidance   = (const float*)d_in[1];
    const float* confidence = (const float*)d_in[2];
    const float* feat_fix   = (const float*)d_in[3];
    const float* aff_scale  = (const float*)d_in[4];
    float* out = (float*)d_out;

    const int threads = 256;
    const int prep_blocks = (Bn * PHWn + TAIL + threads - 1) / threads;
    prep_kernel<<<prep_blocks, threads>>>(feat_init, guidance, confidence,
                                          feat_fix, aff_scale);

    dim3 gridI(Wn / TILE_W, Hn / TILE_H, Bn);   // 10 x 60 x 4 = 2400 blocks
    int srcIsA = 1;
    for (int t = 0; t < PROP_TIME; t++) {
        int last = (t == PROP_TIME - 1) ? 1 : 0;
        iter_kernel<<<gridI, threads>>>(out, srcIsA, last);
        srcIsA ^= 1;
    }
}

// round 17
// speedup vs baseline: 1.2594x; 1.0856x over previous
#include <cuda_runtime.h>
#include <cuda_bf16.h>

// Problem constants
#define Bn 4
#define Hn 480
#define Wn 640
#define HWn (Hn * Wn)          // 307200
#define PWn (Wn + 2)           // 642
#define PHn (Hn + 2)           // 482
#define PHWn (PHn * PWn)       // 309444
#define PROP_TIME 18
#define TAIL 704

// OOB sentinel: row 481 (zero border); +PWn lands in next batch's zero row 0
// or the zero tail for the last batch.
#define SENT_Y (PHn - 1)

// Static scratch: ping-pong padded feature buffers g = f*conf_eff.
__device__ float g_bufA[Bn * PHWn + TAIL];
__device__ float g_bufB[Bn * PHWn + TAIL];
// Packed taps, layout [b][tap][pix], 8 B each, SORTED per pixel by yoff:
//   w0: off(19) | wxq(13)<<19      (off = padded linear index)
//   w1: wyq(13) | affq(signed 19)<<13
__device__ unsigned long long g_taps[(size_t)Bn * 8 * HWn];
// Fused fix/conf: q<0 -> fixed value -q; q>=0 -> conf=q.
__device__ float g_q[Bn * HWn];

// ---------------------------------------------------------------------------
// Precompute (idempotent; replayed each graph launch).
// ---------------------------------------------------------------------------
__global__ __launch_bounds__(256)
void prep_kernel(const float* __restrict__ feat_init,
                 const float* __restrict__ guid,
                 const float* __restrict__ conf,
                 const float* __restrict__ fix,
                 const float* __restrict__ scale_ptr)
{
    int idx = blockIdx.x * blockDim.x + threadIdx.x;
    if (idx >= Bn * PHWn + TAIL) return;

    int b = idx / PHWn;
    int r = idx - b * PHWn;
    int yy = r / PWn;
    int xx = r - yy * PWn;

    bool is_tail = (idx >= Bn * PHWn);
    if (is_tail || yy == 0 || yy == PHn - 1 || xx == 0 || xx == PWn - 1) {
        g_bufA[idx] = 0.0f;
        g_bufB[idx] = 0.0f;
        return;
    }

    int y = yy - 1, x = xx - 1;
    int pix = y * Wn + x;

    // Affinity normalization (guidance channels 16..23)
    float scale = scale_ptr[0] + 1e-8f;
    float inv_scale = 1.0f / scale;
    const float* gbase = guid + ((size_t)b * 24) * HWn + pix;
    float a[8];
    float s = 1e-4f;
#pragma unroll
    for (int k = 0; k < 8; k++) {
        float v = tanhf(gbase[(16 + k) * HWn]) * inv_scale;
        a[k] = v;
        s += fabsf(v);
    }
    s = fmaxf(s, 1.0f);
    float invs = 1.0f / s;

    unsigned long long words[8];
    unsigned int keys[8];
#pragma unroll
    for (int t = 0; t < 8; t++) {
        const int kt = (t < 4) ? t : t + 1;
        const float ky = (float)(kt / 3 - 1);
        const float kx = (float)(kt % 3 - 1);

        float dy = gbase[(2 * t) * HWn];
        float dx = gbase[(2 * t + 1) * HWn];

        float py = (float)y + ky + dy;
        float px = (float)x + kx + dx;
        float y0f = floorf(py);
        float x0f = floorf(px);
        int iy = (int)y0f;
        int ix = (int)x0f;
        float wy = py - y0f;
        float wx = px - x0f;

        bool valid = (iy >= -1) & (iy <= Hn - 1) & (ix >= -1) & (ix <= Wn - 1);
        int yoff = valid ? (iy + 1) : SENT_Y;
        int xoff = valid ? (ix + 1) : 0;
        unsigned int off = (unsigned int)(yoff * PWn + xoff);

        int wxq = min((int)(wx * 8192.0f + 0.5f), 8191);
        int wyq = min((int)(wy * 8192.0f + 0.5f), 8191);
        int affq = (int)rintf(a[t] * invs * 131072.0f);

        unsigned int w0 = off | ((unsigned int)wxq << 19);
        unsigned int w1 = (unsigned int)wyq | ((unsigned int)affq << 13);
        words[t] = ((unsigned long long)w1 << 32) | w0;
        keys[t] = off;   // sort key: target position (row-major => row-dominant)
    }

    // Insertion-sort taps by target offset: makes same-index taps across
    // adjacent pixels hit correlated rows (order statistics), cutting the
    // L1tex lines-per-wavefront of the warp-wide gather.
#pragma unroll
    for (int i2 = 1; i2 < 8; i2++) {
#pragma unroll
        for (int j2 = i2; j2 > 0; j2--) {
            if (keys[j2 - 1] > keys[j2]) {
                unsigned int tk = keys[j2 - 1]; keys[j2 - 1] = keys[j2]; keys[j2] = tk;
                unsigned long long tw = words[j2 - 1]; words[j2 - 1] = words[j2]; words[j2] = tw;
            }
        }
    }

#pragma unroll
    for (int t = 0; t < 8; t++)
        g_taps[(size_t)(b * 8 + t) * HWn + pix] = words[t];

    int gidx = b * HWn + pix;
    float fv = fix[gidx];
    bool m = fv > 0.0f;
    float cf = conf[gidx];
    float f0 = m ? fv : feat_init[gidx];
    float ce = m ? 1.0f : cf;
    g_bufA[idx] = f0 * ce;
    g_q[gidx] = m ? -fv : cf;
}

// ---------------------------------------------------------------------------
// One propagation step: 4 px/thread, scattered gather (no smem), sorted taps.
// ---------------------------------------------------------------------------
__device__ __forceinline__ void do_tap(unsigned long long w,
                                       const float* __restrict__ gIn,
                                       float& asum, float& acc)
{
    unsigned int w0 = (unsigned int)w;
    unsigned int w1 = (unsigned int)(w >> 32);
    unsigned int off = w0 & 0x7FFFFu;
    float wx = (float)(w0 >> 19) * (1.0f / 8192.0f);
    float wy = (float)(w1 & 8191u) * (1.0f / 8192.0f);
    float av = (float)(((int)w1) >> 13) * (1.0f / 131072.0f);

    const float* p = gIn + off;
    float v00 = p[0];
    float v01 = p[1];
    float v10 = p[PWn];
    float v11 = p[PWn + 1];
    float top = fmaf(wx, v01 - v00, v00);
    float bot = fmaf(wx, v11 - v10, v10);
    float v = fmaf(wy, bot - top, top);
    acc = fmaf(av, v, acc);
    asum += av;
}

__global__ __launch_bounds__(256, 4)
void iter_kernel(float* __restrict__ outF, int srcIsA, int write_out)
{
    int i = blockIdx.x * blockDim.x + threadIdx.x;
    if (i >= Bn * HWn / 4) return;
    int p = i * 4;
    int b = p / HWn;
    int r = p - b * HWn;
    int y = r / Wn;
    int x = r - y * Wn;          // multiple of 4; row never crossed (Wn%4==0)

    const float* __restrict__ gIn = (srcIsA ? g_bufA : g_bufB) + (size_t)b * PHWn;
    const unsigned long long* __restrict__ tp = g_taps + (size_t)(b * 8) * HWn + r;

    float acc[4]  = {0.0f, 0.0f, 0.0f, 0.0f};
    float asum[4] = {0.0f, 0.0f, 0.0f, 0.0f};

#pragma unroll
    for (int t = 0; t < 8; t++) {
        // 32 B of taps for 4 consecutive pixels: two 16 B loads.
        ulonglong2 ta = *reinterpret_cast<const ulonglong2*>(tp + (size_t)t * HWn);
        ulonglong2 tb = *reinterpret_cast<const ulonglong2*>(tp + (size_t)t * HWn + 2);
        do_tap(ta.x, gIn, asum[0], acc[0]);
        do_tap(ta.y, gIn, asum[1], acc[1]);
        do_tap(tb.x, gIn, asum[2], acc[2]);
        do_tap(tb.y, gIn, asum[3], acc[3]);
    }

    // Center taps: exact samples; affinity = 1 - sum(aff8).
    int cbase = (y + 1) * PWn + (x + 1);
#pragma unroll
    for (int j = 0; j < 4; j++)
        acc[j] = fmaf(1.0f - asum[j], gIn[cbase + j], acc[j]);

    float4 qv = *reinterpret_cast<const float4*>(g_q + p);
    float q[4] = {qv.x, qv.y, qv.z, qv.w};

    if (write_out) {
        float4 o;
        o.x = (q[0] < 0.0f) ? -q[0] : acc[0];
        o.y = (q[1] < 0.0f) ? -q[1] : acc[1];
        o.z = (q[2] < 0.0f) ? -q[2] : acc[2];
        o.w = (q[3] < 0.0f) ? -q[3] : acc[3];
        *reinterpret_cast<float4*>(outF + p) = o;
    } else {
        float* gOut = (srcIsA ? g_bufB : g_bufA) + (size_t)b * PHWn;
#pragma unroll
        for (int j = 0; j < 4; j++) {
            bool m = q[j] < 0.0f;
            // fixed: g = fix value (conf_eff = 1); else g = acc * conf
            gOut[cbase + j] = m ? -q[j] : acc[j] * q[j];
        }
    }
}

extern "C" void kernel_launch(void* const* d_in, const int* in_sizes, int n_in,
                              void* d_out, int out_size)
{
    const float* feat_init  = (const float*)d_in[0];
    const float* guidance   = (const float*)d_in[1];
    const float* confidence = (const float*)d_in[2];
    const float* feat_fix   = (const float*)d_in[3];
    const float* aff_scale  = (const float*)d_in[4];
    float* out = (float*)d_out;

    const int threads = 256;
    const int prep_blocks = (Bn * PHWn + TAIL + threads - 1) / threads;
    prep_kernel<<<prep_blocks, threads>>>(feat_init, guidance, confidence,
                                          feat_fix, aff_scale);

    const int iter_blocks = (Bn * HWn / 4 + threads - 1) / threads;   // 1200
    int srcIsA = 1;
    for (int t = 0; t < PROP_TIME; t++) {
        int last = (t == PROP_TIME - 1) ? 1 : 0;
        iter_kernel<<<iter_blocks, threads>>>(out, srcIsA, last);
        srcIsA ^= 1;
    }
}